// round 6
// baseline (speedup 1.0000x reference)
#include <cuda_runtime.h>
#include <cuda_fp16.h>
#include <math.h>

#define MM 4096
#define NN 4096
#define KD 512
#define MP 4097               // M+1 (dustbin row/col)
#define ESTRIDE 4128          // row stride (elements); 32-elem multiple
#define KN_SIZE ((size_t)MM*NN)
#define SC_SIZE ((size_t)MP*MP)
#define SCALE_KN 0.04419417382415922f   /* 1/sqrt(512) */
#define MU_IN (1.0f/8192.0f)            /* exp(-log(m+n)) */
#define MU_LAST 0.5f                    /* exp(log(n)-log(m+n)) */
#define EH_SCALE 0.125f                 /* Eh = E/8; uniform scale cancels in fixed point */
#define OUT_FACTOR 1024.0f              /* 8192 * (1/8): euh = 8*eu_true */
#define NBLK 128                        /* persistent grid: 1024 warps, 4 rows/warp exact */

// ---------------- device scratch (no allocations allowed) ----------------
__device__ __align__(128) float  g_proj[(size_t)(MM + NN) * KD];      // m0 | m1 (16.8 MB)
__device__ __align__(128) float  g_E  [(size_t)MP * ESTRIDE + 64];    // exp(Kn) fp32 (67.7 MB)
__device__ __align__(128) __half g_Eh [(size_t)MP * ESTRIDE + 64];    // exp(Kn)/8 fp16 (33.8 MB)
__device__ __align__(128) __half g_EhT[(size_t)MP * ESTRIDE + 64];    // transpose of g_Eh
__device__ __align__(16)  float  g_eu[MP];    // = 8 * eu_true
__device__ __align__(16)  float  g_ev[MP];    // = ev_true
__device__ float g_trow[MM];
__device__ float g_tcol[NN];
__device__ unsigned g_bar_count = 0;
__device__ unsigned g_bar_phase = 0;

// ---------------- SGEMM: C[M x N] = A[M x K] * B[N x K]^T ----------------
// 128x128 tile, BK=8, 256 threads, 8x8/thread, register-prefetch double buffer.
template<bool BIAS, bool WRITE_E>
__global__ __launch_bounds__(256) void sgemm_kernel(
    const float* __restrict__ A0, const float* __restrict__ A1, int a_split,
    const float* __restrict__ B, const float* __restrict__ bias,
    float* __restrict__ C, int ldc, int K, float scale)
{
    __shared__ __align__(16) float As[8][132];
    __shared__ __align__(16) float Bs[8][132];
    const int tid = threadIdx.x;
    const int bm = blockIdx.y * 128;
    const int bn = blockIdx.x * 128;
    const int lr = tid >> 1;            // 0..127
    const int lc = (tid & 1) * 4;       // 0 or 4
    const int grow = bm + lr;
    const float* Arow = (grow < a_split) ? (A0 + (size_t)grow * K)
                                         : (A1 + (size_t)(grow - a_split) * K);
    const float* Brow = B + (size_t)(bn + lr) * K;
    const int ty = tid >> 4, tx = tid & 15;

    float acc[8][8];
    #pragma unroll
    for (int m = 0; m < 8; m++)
        #pragma unroll
        for (int n = 0; n < 8; n++) acc[m][n] = 0.f;

    float4 av = *(const float4*)(Arow + lc);
    float4 bv = *(const float4*)(Brow + lc);

    for (int k0 = 0; k0 < K; k0 += 8) {
        As[lc + 0][lr] = av.x; As[lc + 1][lr] = av.y;
        As[lc + 2][lr] = av.z; As[lc + 3][lr] = av.w;
        Bs[lc + 0][lr] = bv.x; Bs[lc + 1][lr] = bv.y;
        Bs[lc + 2][lr] = bv.z; Bs[lc + 3][lr] = bv.w;
        __syncthreads();
        if (k0 + 8 < K) {                 // prefetch next tile before compute
            av = *(const float4*)(Arow + k0 + 8 + lc);
            bv = *(const float4*)(Brow + k0 + 8 + lc);
        }
        #pragma unroll
        for (int kk = 0; kk < 8; kk++) {
            float ra[8], rb[8];
            *(float4*)&ra[0] = *(const float4*)&As[kk][ty * 8];
            *(float4*)&ra[4] = *(const float4*)&As[kk][ty * 8 + 4];
            *(float4*)&rb[0] = *(const float4*)&Bs[kk][tx * 8];
            *(float4*)&rb[4] = *(const float4*)&Bs[kk][tx * 8 + 4];
            #pragma unroll
            for (int m = 0; m < 8; m++)
                #pragma unroll
                for (int n = 0; n < 8; n++) acc[m][n] += ra[m] * rb[n];
        }
        __syncthreads();
    }
    #pragma unroll
    for (int m = 0; m < 8; m++) {
        const int gi = bm + ty * 8 + m;
        #pragma unroll
        for (int n = 0; n < 8; n++) {
            const int gj = bn + tx * 8 + n;
            float c = acc[m][n] * scale;
            if (BIAS) c += bias[gj];
            C[(size_t)gi * ldc + gj] = c;
            if (WRITE_E) {
                float e = expf(c);
                g_E [(size_t)gi * ESTRIDE + gj] = e;
                g_Eh[(size_t)gi * ESTRIDE + gj] = __float2half(e * EH_SCALE);
            }
        }
    }
}

// ---------------- init: fp32 E borders (for epilogue) and ev = 1 ----------------
__global__ void init_kernel(const float* __restrict__ alpha_p) {
    const int i = blockIdx.x * 256 + threadIdx.x;
    const float ea = expf(alpha_p[0]);
    if (i < MP) {
        g_E[(size_t)MM * ESTRIDE + i] = ea;   // bottom dustbin row (incl. corner)
        g_E[(size_t)i * ESTRIDE + NN] = ea;   // right dustbin column
        g_ev[i] = 1.0f;
    }
}

// ---------------- transpose: g_EhT[j][i] = g_Eh[i][j], 64x64 half tiles ----------------
// Only the 4096x4096 interior is ever read from EhT (dustbin handled analytically).
__global__ __launch_bounds__(256) void transpose_kernel() {
    __shared__ __half tile[64][72];
    const int i0 = blockIdx.y * 64;
    const int j0 = blockIdx.x * 64;
    const int w = threadIdx.x >> 5, l = threadIdx.x & 31;

    const __half2* __restrict__ src2 = (const __half2*)g_Eh;
    #pragma unroll
    for (int r = w; r < 64; r += 8) {
        __half2 v = src2[(size_t)(i0 + r) * (ESTRIDE / 2) + (j0 >> 1) + l];
        tile[2 * l + 0][r] = __low2half(v);
        tile[2 * l + 1][r] = __high2half(v);
    }
    __syncthreads();
    __half2* __restrict__ dst2 = (__half2*)g_EhT;
    #pragma unroll
    for (int r = w; r < 64; r += 8)
        dst2[(size_t)(j0 + r) * (ESTRIDE / 2) + (i0 >> 1) + l] =
            __halves2half2(tile[r][2 * l], tile[r][2 * l + 1]);
}

// ---------------- software grid barrier (all NBLK blocks co-resident) ----------------
__device__ __forceinline__ void grid_barrier() {
    __syncthreads();
    if (threadIdx.x == 0) {
        volatile unsigned* ph = &g_bar_phase;
        const unsigned cur = *ph;
        __threadfence();
        if (atomicAdd(&g_bar_count, 1u) == NBLK - 1u) {
            atomicExch(&g_bar_count, 0u);
            __threadfence();
            atomicAdd(&g_bar_phase, 1u);     // release
        } else {
            while (*ph == cur) { __nanosleep(64); }
        }
        __threadfence();
    }
    __syncthreads();
}

// ---------------- one Sinkhorn half-pass over the 4096 interior rows ----------------
// dst_i = mass / (Mat[i,0:4096] . vec + ea8*vec[4096]); warp processes 4 contiguous rows.
__device__ __forceinline__ void half_pass(
    const __half* __restrict__ Mat, const float* __restrict__ svec,
    float* __restrict__ dst, int row0, int lane, float tailv)
{
    #pragma unroll
    for (int r = 0; r < 4; r++) {
        const int i = row0 + r;
        const __half2* __restrict__ Mr = ((const __half2*)Mat) + (size_t)i * (ESTRIDE / 2);
        float s = 0.f;
        #pragma unroll 16
        for (int t = lane; t < 2048; t += 32) {
            float2 e = __half22float2(Mr[t]);
            float2 v = *(const float2*)&svec[2 * t];
            s += e.x * v.x + e.y * v.y;
        }
        #pragma unroll
        for (int off = 16; off; off >>= 1) s += __shfl_down_sync(0xffffffffu, s, off);
        if (lane == 0) __stcg(&dst[i], MU_IN / (s + tailv));
    }
}

// ---------------- persistent Sinkhorn: all 100 iterations in one launch ----------------
__global__ __launch_bounds__(256) void sinkhorn_kernel(const float* __restrict__ alpha_p) {
    __shared__ __align__(16) float sv[MP + 3];
    __shared__ float wsum[8];
    const int tid  = threadIdx.x;
    const int warp = tid >> 5, lane = tid & 31;
    const int row0 = blockIdx.x * 32 + warp * 4;     // 4 contiguous rows per warp
    const float ea8 = expf(alpha_p[0]) * EH_SCALE;   // e^alpha / 8

    for (int it = 0; it < 100; it++) {
        // ---- stage ev (L2-coherent) + block total for analytic dustbin ----
        float part = 0.f;
        for (int t = tid; t < MP; t += 256) { float x = __ldcg(&g_ev[t]); sv[t] = x; part += x; }
        #pragma unroll
        for (int off = 16; off; off >>= 1) part += __shfl_down_sync(0xffffffffu, part, off);
        if (lane == 0) wsum[warp] = part;
        __syncthreads();
        if (blockIdx.x == 0 && tid == 0) {
            float tot = 0.f;
            #pragma unroll
            for (int r = 0; r < 8; r++) tot += wsum[r];
            __stcg(&g_eu[MM], MU_LAST / (ea8 * tot));   // dustbin row: exact fp32
        }
        half_pass(g_Eh, sv, g_eu, row0, lane, ea8 * sv[4096]);
        grid_barrier();

        // ---- stage eu, col phase as coalesced pass over EhT ----
        part = 0.f;
        for (int t = tid; t < MP; t += 256) { float x = __ldcg(&g_eu[t]); sv[t] = x; part += x; }
        #pragma unroll
        for (int off = 16; off; off >>= 1) part += __shfl_down_sync(0xffffffffu, part, off);
        if (lane == 0) wsum[warp] = part;
        __syncthreads();
        if (blockIdx.x == 0 && tid == 0) {
            float tot = 0.f;
            #pragma unroll
            for (int r = 0; r < 8; r++) tot += wsum[r];
            __stcg(&g_ev[NN], MU_LAST / (ea8 * tot));   // dustbin col: exact fp32
        }
        half_pass(g_EhT, sv, g_ev, row0, lane, ea8 * sv[4096]);
        grid_barrier();
    }
}

// ---------------- mutual top-3 helpers ----------------
__device__ __forceinline__ void ins3(float x, float& a, float& b, float& c) {
    if (x > c) {
        if (x > b) { c = b; if (x > a) { b = a; a = x; } else b = x; }
        else c = x;
    }
}

// ---------------- fused scores write + row top-3 (warp per row) ----------------
__global__ __launch_bounds__(256) void scores_rowtop3(float* __restrict__ out) {
    const int w = threadIdx.x >> 5, lane = threadIdx.x & 31;
    const int i = blockIdx.x * 8 + w;
    if (i >= MP) return;
    const float* __restrict__ Er = g_E + (size_t)i * ESTRIDE;
    float* __restrict__ orow = out + (size_t)i * MP;
    const float eui = g_eu[i] * OUT_FACTOR;
    float a = -1e30f, b = -1e30f, c = -1e30f;
    for (int j = lane; j < NN; j += 32) {
        float s = Er[j] * g_ev[j] * eui;
        orow[j] = s;
        ins3(s, a, b, c);
    }
    if (lane == 0) orow[NN] = Er[NN] * g_ev[NN] * eui;   // dustbin col
    if (i == MM) return;                                  // no top3 for dustbin row
    #pragma unroll
    for (int off = 16; off; off >>= 1) {
        float oa = __shfl_down_sync(0xffffffffu, a, off);
        float ob = __shfl_down_sync(0xffffffffu, b, off);
        float oc = __shfl_down_sync(0xffffffffu, c, off);
        ins3(oa, a, b, c); ins3(ob, a, b, c); ins3(oc, a, b, c);
    }
    if (lane == 0) g_trow[i] = c;
}

__global__ __launch_bounds__(256) void col_top3() {
    const int jj = threadIdx.x & 31, ii = threadIdx.x >> 5;
    const int j = blockIdx.x * 32 + jj;            // grid.x = 128 -> j < 4096
    const float evj = g_ev[j] * OUT_FACTOR;
    float a = -1e30f, b = -1e30f, c = -1e30f;
    #pragma unroll 8
    for (int i = ii; i < MM; i += 8)
        ins3(g_E[(size_t)i * ESTRIDE + j] * g_eu[i] * evj, a, b, c);
    __shared__ float ra[8][33], rb[8][33], rc[8][33];
    ra[ii][jj] = a; rb[ii][jj] = b; rc[ii][jj] = c;
    __syncthreads();
    if (threadIdx.x < 32) {
        float A = -1e30f, B = -1e30f, C = -1e30f;
        #pragma unroll
        for (int r = 0; r < 8; r++) {
            ins3(ra[r][threadIdx.x], A, B, C);
            ins3(rb[r][threadIdx.x], A, B, C);
            ins3(rc[r][threadIdx.x], A, B, C);
        }
        g_tcol[blockIdx.x * 32 + threadIdx.x] = C;
    }
}

__global__ void assign_kernel(float* __restrict__ out) {
    const int i = blockIdx.y;
    const int j = blockIdx.x * 256 + threadIdx.x;   // grid.x = 16
    const float s = g_E[(size_t)i * ESTRIDE + j] * g_eu[i] * g_ev[j] * OUT_FACTOR;
    const bool a = (s > 0.05f) && (s >= g_trow[i]) && (s >= g_tcol[j]);
    out[(size_t)i * NN + j] = a ? 1.0f : 0.0f;
}

// ---------------- launch ----------------
extern "C" void kernel_launch(void* const* d_in, const int* in_sizes, int n_in,
                              void* d_out, int out_size) {
    const float* desc0 = (const float*)d_in[0];
    const float* desc1 = (const float*)d_in[1];
    const float* W     = (const float*)d_in[2];
    const float* b     = (const float*)d_in[3];
    const float* alpha = (const float*)d_in[4];

    float* out   = (float*)d_out;
    float* outKn = out;
    float* outSc = out + KN_SIZE;
    float* outAs = outSc + SC_SIZE;

    float* gproj = nullptr; cudaGetSymbolAddress((void**)&gproj, g_proj);

    // 1) projection: [8192 x 512] = [desc0;desc1] @ W^T + b
    sgemm_kernel<true, false><<<dim3(KD / 128, (MM + NN) / 128), 256>>>(
        desc0, desc1, MM, W, b, gproj, KD, KD, 1.0f);

    // 2) Kn = m0 @ m1^T / sqrt(512); fused E = exp(Kn) (fp32 + fp16/8 mirror)
    sgemm_kernel<false, true><<<dim3(NN / 128, MM / 128), 256>>>(
        gproj, gproj, 1 << 30, gproj + (size_t)MM * KD, nullptr,
        outKn, NN, KD, SCALE_KN);

    // 3) fp32 E borders + ev init, then build transposed fp16 mirror (interior)
    init_kernel<<<(MP + 255) / 256, 256>>>(alpha);
    transpose_kernel<<<dim3(64, 64), 256>>>();

    // 4) 100 Sinkhorn iterations in ONE persistent launch (analytic dustbin)
    sinkhorn_kernel<<<NBLK, 256>>>(alpha);

    // 5) outputs: scores (+ row top3 fused), col top3, assignment
    scores_rowtop3<<<(MP + 7) / 8, 256>>>(outSc);
    col_top3<<<NN / 32, 256>>>();
    assign_kernel<<<dim3(NN / 256, MM), 256>>>(outAs);
}

// round 9
// speedup vs baseline: 1.7067x; 1.7067x over previous
#include <cuda_runtime.h>
#include <cuda_fp16.h>
#include <math.h>

#define MM 4096
#define NN 4096
#define KD 512
#define MP 4097               // M+1 (dustbin row/col)
#define ESTRIDE 4128          // row stride (elements); 32-elem multiple
#define KN_SIZE ((size_t)MM*NN)
#define SC_SIZE ((size_t)MP*MP)
#define SCALE_KN 0.04419417382415922f   /* 1/sqrt(512) */
#define MU_IN (1.0f/8192.0f)            /* exp(-log(m+n)) */
#define MU_LAST 0.5f                    /* exp(log(n)-log(m+n)) */
#define EH_SCALE 0.125f                 /* Eh = E/8; uniform scale cancels in fixed point */
#define OUT_FACTOR 1024.0f              /* 8192 * (1/8): euh = 8*eu_true */
#define NBLK 128                        /* persistent grid: 1024 warps, 4 rows/warp exact */

// ---------------- device scratch (no allocations allowed) ----------------
__device__ __align__(128) float  g_proj[(size_t)(MM + NN) * KD];      // m0 | m1 (16.8 MB)
__device__ __align__(128) float  g_E  [(size_t)MP * ESTRIDE + 64];    // exp(Kn) fp32 (67.7 MB)
__device__ __align__(128) __half g_Eh [(size_t)MP * ESTRIDE + 64];    // exp(Kn)/8 fp16 (33.8 MB)
__device__ __align__(128) __half g_EhT[(size_t)MP * ESTRIDE + 64];    // transpose of g_Eh
__device__ __align__(16)  float  g_eu[MP];    // = 8 * eu_true
__device__ __align__(16)  float  g_ev[MP];    // = ev_true
__device__ float g_trow[MM];
__device__ float g_tcol[NN];
__device__ unsigned g_bar_count = 0;
__device__ unsigned g_bar_phase = 0;

// ---------------- SGEMM: C[M x N] = A[M x K] * B[N x K]^T ----------------
// 128x128 tile, BK=8, 256 threads, 8x8/thread, register-prefetch double buffer.
template<bool BIAS, bool WRITE_E>
__global__ __launch_bounds__(256) void sgemm_kernel(
    const float* __restrict__ A0, const float* __restrict__ A1, int a_split,
    const float* __restrict__ B, const float* __restrict__ bias,
    float* __restrict__ C, int ldc, int K, float scale)
{
    __shared__ __align__(16) float As[8][132];
    __shared__ __align__(16) float Bs[8][132];
    const int tid = threadIdx.x;
    const int bm = blockIdx.y * 128;
    const int bn = blockIdx.x * 128;
    const int lr = tid >> 1;            // 0..127
    const int lc = (tid & 1) * 4;       // 0 or 4
    const int grow = bm + lr;
    const float* Arow = (grow < a_split) ? (A0 + (size_t)grow * K)
                                         : (A1 + (size_t)(grow - a_split) * K);
    const float* Brow = B + (size_t)(bn + lr) * K;
    const int ty = tid >> 4, tx = tid & 15;

    float acc[8][8];
    #pragma unroll
    for (int m = 0; m < 8; m++)
        #pragma unroll
        for (int n = 0; n < 8; n++) acc[m][n] = 0.f;

    float4 av = *(const float4*)(Arow + lc);
    float4 bv = *(const float4*)(Brow + lc);

    for (int k0 = 0; k0 < K; k0 += 8) {
        As[lc + 0][lr] = av.x; As[lc + 1][lr] = av.y;
        As[lc + 2][lr] = av.z; As[lc + 3][lr] = av.w;
        Bs[lc + 0][lr] = bv.x; Bs[lc + 1][lr] = bv.y;
        Bs[lc + 2][lr] = bv.z; Bs[lc + 3][lr] = bv.w;
        __syncthreads();
        if (k0 + 8 < K) {                 // prefetch next tile before compute
            av = *(const float4*)(Arow + k0 + 8 + lc);
            bv = *(const float4*)(Brow + k0 + 8 + lc);
        }
        #pragma unroll
        for (int kk = 0; kk < 8; kk++) {
            float ra[8], rb[8];
            *(float4*)&ra[0] = *(const float4*)&As[kk][ty * 8];
            *(float4*)&ra[4] = *(const float4*)&As[kk][ty * 8 + 4];
            *(float4*)&rb[0] = *(const float4*)&Bs[kk][tx * 8];
            *(float4*)&rb[4] = *(const float4*)&Bs[kk][tx * 8 + 4];
            #pragma unroll
            for (int m = 0; m < 8; m++)
                #pragma unroll
                for (int n = 0; n < 8; n++) acc[m][n] += ra[m] * rb[n];
        }
        __syncthreads();
    }
    #pragma unroll
    for (int m = 0; m < 8; m++) {
        const int gi = bm + ty * 8 + m;
        #pragma unroll
        for (int n = 0; n < 8; n++) {
            const int gj = bn + tx * 8 + n;
            float c = acc[m][n] * scale;
            if (BIAS) c += bias[gj];
            C[(size_t)gi * ldc + gj] = c;
            if (WRITE_E) {
                float e = __expf(c);      // MUFU.EX2 path; rel err ~1e-6 << budget
                g_E [(size_t)gi * ESTRIDE + gj] = e;
                g_Eh[(size_t)gi * ESTRIDE + gj] = __float2half(e * EH_SCALE);
            }
        }
    }
}

// ---------------- transpose (EhT[j][i] = Eh[i][j]) + fused border/ev init ----------------
__global__ __launch_bounds__(256) void transpose_kernel(const float* __restrict__ alpha_p) {
    __shared__ __half tile[64][72];
    const int i0 = blockIdx.y * 64;
    const int j0 = blockIdx.x * 64;
    const int w = threadIdx.x >> 5, l = threadIdx.x & 31;

    if (blockIdx.x == 0 && blockIdx.y == 0) {
        const float ea = expf(alpha_p[0]);
        for (int i = threadIdx.x; i < MP; i += 256) {
            g_E[(size_t)MM * ESTRIDE + i] = ea;   // bottom dustbin row (incl. corner)
            g_E[(size_t)i * ESTRIDE + NN] = ea;   // right dustbin column
            g_ev[i] = 1.0f;
        }
    }

    const __half2* __restrict__ src2 = (const __half2*)g_Eh;
    #pragma unroll
    for (int r = w; r < 64; r += 8) {
        __half2 v = src2[(size_t)(i0 + r) * (ESTRIDE / 2) + (j0 >> 1) + l];
        tile[2 * l + 0][r] = __low2half(v);
        tile[2 * l + 1][r] = __high2half(v);
    }
    __syncthreads();
    __half2* __restrict__ dst2 = (__half2*)g_EhT;
    #pragma unroll
    for (int r = w; r < 64; r += 8)
        dst2[(size_t)(j0 + r) * (ESTRIDE / 2) + (i0 >> 1) + l] =
            __halves2half2(tile[r][2 * l], tile[r][2 * l + 1]);
}

// ---------------- software grid barrier (all NBLK blocks co-resident) ----------------
__device__ __forceinline__ void grid_barrier() {
    __syncthreads();
    if (threadIdx.x == 0) {
        volatile unsigned* ph = &g_bar_phase;
        const unsigned cur = *ph;
        __threadfence();
        if (atomicAdd(&g_bar_count, 1u) == NBLK - 1u) {
            atomicExch(&g_bar_count, 0u);
            __threadfence();
            atomicAdd(&g_bar_phase, 1u);     // release
        } else {
            while (*ph == cur) { __nanosleep(32); }
        }
        __threadfence();
    }
    __syncthreads();
}

__device__ __forceinline__ float warp_red(float s) {
    #pragma unroll
    for (int off = 16; off; off >>= 1) s += __shfl_down_sync(0xffffffffu, s, off);
    return s;
}

// ---------------- one Sinkhorn half-pass over the 4096 interior rows ----------------
// 4-row fused, 16B loads: two float4 LDS of the vector feed 4 uint4 (8-half) row loads.
// dst_i = MU_IN / (Mat[i,0:4096].vec + tailv)
__device__ __forceinline__ void half_pass(
    const __half* __restrict__ Mat, const float* __restrict__ svec,
    float* __restrict__ dst, int row0, int lane, float tailv)
{
    const uint4* __restrict__ p0 = (const uint4*)(Mat + (size_t)(row0 + 0) * ESTRIDE);
    const uint4* __restrict__ p1 = (const uint4*)(Mat + (size_t)(row0 + 1) * ESTRIDE);
    const uint4* __restrict__ p2 = (const uint4*)(Mat + (size_t)(row0 + 2) * ESTRIDE);
    const uint4* __restrict__ p3 = (const uint4*)(Mat + (size_t)(row0 + 3) * ESTRIDE);
    float s0 = 0.f, s1 = 0.f, s2 = 0.f, s3 = 0.f;
    #pragma unroll 4
    for (int t = lane; t < 512; t += 32) {       // 16 iters/lane; 8 halves/row each
        uint4 a0 = p0[t], a1 = p1[t], a2 = p2[t], a3 = p3[t];
        float4 v0 = *(const float4*)&svec[8 * t];
        float4 v1 = *(const float4*)&svec[8 * t + 4];
        float2 x;
        x = __half22float2(*(const __half2*)&a0.x); s0 += x.x * v0.x + x.y * v0.y;
        x = __half22float2(*(const __half2*)&a0.y); s0 += x.x * v0.z + x.y * v0.w;
        x = __half22float2(*(const __half2*)&a0.z); s0 += x.x * v1.x + x.y * v1.y;
        x = __half22float2(*(const __half2*)&a0.w); s0 += x.x * v1.z + x.y * v1.w;
        x = __half22float2(*(const __half2*)&a1.x); s1 += x.x * v0.x + x.y * v0.y;
        x = __half22float2(*(const __half2*)&a1.y); s1 += x.x * v0.z + x.y * v0.w;
        x = __half22float2(*(const __half2*)&a1.z); s1 += x.x * v1.x + x.y * v1.y;
        x = __half22float2(*(const __half2*)&a1.w); s1 += x.x * v1.z + x.y * v1.w;
        x = __half22float2(*(const __half2*)&a2.x); s2 += x.x * v0.x + x.y * v0.y;
        x = __half22float2(*(const __half2*)&a2.y); s2 += x.x * v0.z + x.y * v0.w;
        x = __half22float2(*(const __half2*)&a2.z); s2 += x.x * v1.x + x.y * v1.y;
        x = __half22float2(*(const __half2*)&a2.w); s2 += x.x * v1.z + x.y * v1.w;
        x = __half22float2(*(const __half2*)&a3.x); s3 += x.x * v0.x + x.y * v0.y;
        x = __half22float2(*(const __half2*)&a3.y); s3 += x.x * v0.z + x.y * v0.w;
        x = __half22float2(*(const __half2*)&a3.z); s3 += x.x * v1.x + x.y * v1.y;
        x = __half22float2(*(const __half2*)&a3.w); s3 += x.x * v1.z + x.y * v1.w;
    }
    s0 = warp_red(s0); s1 = warp_red(s1); s2 = warp_red(s2); s3 = warp_red(s3);
    if (lane == 0) {
        __stcg(&dst[row0 + 0], MU_IN / (s0 + tailv));
        __stcg(&dst[row0 + 1], MU_IN / (s1 + tailv));
        __stcg(&dst[row0 + 2], MU_IN / (s2 + tailv));
        __stcg(&dst[row0 + 3], MU_IN / (s3 + tailv));
    }
}

// ---------------- persistent Sinkhorn: all 100 iterations in one launch ----------------
__global__ __launch_bounds__(256) void sinkhorn_kernel(const float* __restrict__ alpha_p) {
    __shared__ __align__(16) float sv[MP + 7];
    __shared__ float wsum[8];
    const int tid  = threadIdx.x;
    const int warp = tid >> 5, lane = tid & 31;
    const int row0 = blockIdx.x * 32 + warp * 4;     // 4 contiguous rows per warp
    const float ea8 = __expf(alpha_p[0]) * EH_SCALE; // e^alpha / 8 (matches Eh scale)

    for (int it = 0; it < 100; it++) {
        // ---- stage ev (L2-coherent) + block total for analytic dustbin ----
        float part = 0.f;
        for (int t = tid; t < MP; t += 256) { float x = __ldcg(&g_ev[t]); sv[t] = x; part += x; }
        part = warp_red(part);
        if (lane == 0) wsum[warp] = part;
        __syncthreads();
        if (blockIdx.x == 0 && tid == 0) {
            float tot = 0.f;
            #pragma unroll
            for (int r = 0; r < 8; r++) tot += wsum[r];
            __stcg(&g_eu[MM], MU_LAST / (ea8 * tot));   // dustbin row: exact fp32
        }
        half_pass(g_Eh, sv, g_eu, row0, lane, ea8 * sv[4096]);
        grid_barrier();

        // ---- stage eu, col phase as coalesced pass over EhT ----
        part = 0.f;
        for (int t = tid; t < MP; t += 256) { float x = __ldcg(&g_eu[t]); sv[t] = x; part += x; }
        part = warp_red(part);
        if (lane == 0) wsum[warp] = part;
        __syncthreads();
        if (blockIdx.x == 0 && tid == 0) {
            float tot = 0.f;
            #pragma unroll
            for (int r = 0; r < 8; r++) tot += wsum[r];
            __stcg(&g_ev[NN], MU_LAST / (ea8 * tot));   // dustbin col: exact fp32
        }
        half_pass(g_EhT, sv, g_ev, row0, lane, ea8 * sv[4096]);
        grid_barrier();
    }
}

// ---------------- mutual top-3 helpers ----------------
__device__ __forceinline__ void ins3(float x, float& a, float& b, float& c) {
    if (x > c) {
        if (x > b) { c = b; if (x > a) { b = a; a = x; } else b = x; }
        else c = x;
    }
}

// ---------------- fused scores write + row top-3 (warp per row) ----------------
__global__ __launch_bounds__(256) void scores_rowtop3(float* __restrict__ out) {
    const int w = threadIdx.x >> 5, lane = threadIdx.x & 31;
    const int i = blockIdx.x * 8 + w;
    if (i >= MP) return;
    const float* __restrict__ Er = g_E + (size_t)i * ESTRIDE;
    float* __restrict__ orow = out + (size_t)i * MP;
    const float eui = g_eu[i] * OUT_FACTOR;
    float a = -1e30f, b = -1e30f, c = -1e30f;
    #pragma unroll 4
    for (int j = lane; j < NN; j += 32) {
        float s = Er[j] * g_ev[j] * eui;
        orow[j] = s;
        ins3(s, a, b, c);
    }
    if (lane == 0) orow[NN] = Er[NN] * g_ev[NN] * eui;   // dustbin col
    if (i == MM) return;                                  // no top3 for dustbin row
    #pragma unroll
    for (int off = 16; off; off >>= 1) {
        float oa = __shfl_down_sync(0xffffffffu, a, off);
        float ob = __shfl_down_sync(0xffffffffu, b, off);
        float oc = __shfl_down_sync(0xffffffffu, c, off);
        ins3(oa, a, b, c); ins3(ob, a, b, c); ins3(oc, a, b, c);
    }
    if (lane == 0) g_trow[i] = c;
}

__global__ __launch_bounds__(256) void col_top3() {
    const int jj = threadIdx.x & 31, ii = threadIdx.x >> 5;
    const int j = blockIdx.x * 32 + jj;            // grid.x = 128 -> j < 4096
    const float evj = g_ev[j] * OUT_FACTOR;
    float a = -1e30f, b = -1e30f, c = -1e30f;
    #pragma unroll 8
    for (int i = ii; i < MM; i += 8)
        ins3(g_E[(size_t)i * ESTRIDE + j] * g_eu[i] * evj, a, b, c);
    __shared__ float ra[8][33], rb[8][33], rc[8][33];
    ra[ii][jj] = a; rb[ii][jj] = b; rc[ii][jj] = c;
    __syncthreads();
    if (threadIdx.x < 32) {
        float A = -1e30f, B = -1e30f, C = -1e30f;
        #pragma unroll
        for (int r = 0; r < 8; r++) {
            ins3(ra[r][threadIdx.x], A, B, C);
            ins3(rb[r][threadIdx.x], A, B, C);
            ins3(rc[r][threadIdx.x], A, B, C);
        }
        g_tcol[blockIdx.x * 32 + threadIdx.x] = C;
    }
}

__global__ void assign_kernel(float* __restrict__ out) {
    const int i = blockIdx.y;
    const int j = blockIdx.x * 256 + threadIdx.x;   // grid.x = 16
    const float s = g_E[(size_t)i * ESTRIDE + j] * g_eu[i] * g_ev[j] * OUT_FACTOR;
    const bool a = (s > 0.05f) && (s >= g_trow[i]) && (s >= g_tcol[j]);
    out[(size_t)i * NN + j] = a ? 1.0f : 0.0f;
}

// ---------------- launch ----------------
extern "C" void kernel_launch(void* const* d_in, const int* in_sizes, int n_in,
                              void* d_out, int out_size) {
    const float* desc0 = (const float*)d_in[0];
    const float* desc1 = (const float*)d_in[1];
    const float* W     = (const float*)d_in[2];
    const float* b     = (const float*)d_in[3];
    const float* alpha = (const float*)d_in[4];

    float* out   = (float*)d_out;
    float* outKn = out;
    float* outSc = out + KN_SIZE;
    float* outAs = outSc + SC_SIZE;

    float* gproj = nullptr; cudaGetSymbolAddress((void**)&gproj, g_proj);

    // 1) projection: [8192 x 512] = [desc0;desc1] @ W^T + b
    sgemm_kernel<true, false><<<dim3(KD / 128, (MM + NN) / 128), 256>>>(
        desc0, desc1, MM, W, b, gproj, KD, KD, 1.0f);

    // 2) Kn = m0 @ m1^T / sqrt(512); fused E = exp(Kn) (fp32 + fp16/8 mirror)
    sgemm_kernel<false, true><<<dim3(NN / 128, MM / 128), 256>>>(
        gproj, gproj, 1 << 30, gproj + (size_t)MM * KD, nullptr,
        outKn, NN, KD, SCALE_KN);

    // 3) transpose fp16 mirror + fused border/ev init
    transpose_kernel<<<dim3(64, 64), 256>>>(alpha);

    // 4) 100 Sinkhorn iterations in ONE persistent launch (analytic dustbin)
    sinkhorn_kernel<<<NBLK, 256>>>(alpha);

    // 5) outputs: scores (+ row top3 fused), col top3, assignment
    scores_rowtop3<<<(MP + 7) / 8, 256>>>(outSc);
    col_top3<<<NN / 32, 256>>>();
    assign_kernel<<<dim3(NN / 256, MM), 256>>>(outAs);
}